// round 4
// baseline (speedup 1.0000x reference)
#include <cuda_runtime.h>

typedef unsigned long long ull;

// Scratch: processed states, natural layout [4096 rows x 16 floats] = 256 KB.
__device__ __align__(16) float g_P[4096 * 16];

__device__ __forceinline__ ull pack2(float lo, float hi) {
    ull r; asm("mov.b64 %0, {%1, %2};" : "=l"(r) : "f"(lo), "f"(hi)); return r;
}
__device__ __forceinline__ float hadd2(ull v) {
    float lo, hi; asm("mov.b64 {%0, %1}, %2;" : "=f"(lo), "=f"(hi) : "l"(v));
    return lo + hi;
}
// Packed dual-FMA (sm_100+ only; 2x fp32 FMA throughput vs FFMA-3reg)
__device__ __forceinline__ ull fma2(ull a, ull b, ull c) {
    ull d; asm("fma.rn.f32x2 %0, %1, %2, %3;" : "=l"(d) : "l"(a), "l"(b), "l"(c)); return d;
}

// ---------------------------------------------------------------------------
// Kernel 1: per-token quantum circuit -> g_P (natural layout)
// ---------------------------------------------------------------------------
__global__ void prep_kernel(const int* __restrict__ ids,
                            const int* __restrict__ mask,
                            const float* __restrict__ We,
                            const float* __restrict__ gates,
                            int BS, int depth, int S, int B) {
    __shared__ float sg[2 * 256];
    for (int i = threadIdx.x; i < depth * 256; i += blockDim.x) sg[i] = gates[i];
    __syncthreads();

    int m = blockIdx.x * blockDim.x + threadIdx.x;
    if (m >= BS) return;

    int tok = ids[m];
    float e[16], st[16];
    const float4* wr = (const float4*)(We + (size_t)tok * 16);
#pragma unroll
    for (int q = 0; q < 4; q++) {
        float4 v = wr[q];
        e[4*q+0] = v.x; e[4*q+1] = v.y; e[4*q+2] = v.z; e[4*q+3] = v.w;
    }
    float nrm = 0.f;
#pragma unroll
    for (int k = 0; k < 16; k++) nrm += e[k] * e[k];
    float inv = 1.f / (sqrtf(nrm) + 1e-12f);
#pragma unroll
    for (int k = 0; k < 16; k++) { e[k] *= inv; st[k] = e[k]; }

    for (int l = 0; l < depth; l++) {
        float tmp[16];
#pragma unroll
        for (int o = 0; o < 16; o++) {
            float acc = 0.f;
#pragma unroll
            for (int d = 0; d < 16; d++) acc += st[d] * sg[l*256 + o*16 + d];
            tmp[o] = acc;
        }
        float s2 = 0.f;
#pragma unroll
        for (int o = 0; o < 16; o++) {
            // (1-DECOHERENCE)*(1-DEPOL)*x + DEPOL/dim
            float x = tmp[o] * (0.99f * 0.99f) + (0.01f / 16.f);
            st[o] = x; s2 += x * x;
        }
        inv = 1.f / (sqrtf(s2) + 1e-12f);
#pragma unroll
        for (int o = 0; o < 16; o++) st[o] *= inv;
    }
#pragma unroll
    for (int k = 0; k < 16; k++) st[k] = st[k] * 0.99f + (0.01f / 16.f);

    int s = m % S;
    bool ap = true;
    for (int b = 0; b < B; b++) ap = ap && (mask[b * S + s] != 0);

    float4* dst = (float4*)(g_P + (size_t)m * 16);
#pragma unroll
    for (int q = 0; q < 4; q++) {
        dst[q] = make_float4(ap ? st[4*q]   : e[4*q],
                             ap ? st[4*q+1] : e[4*q+1],
                             ap ? st[4*q+2] : e[4*q+2],
                             ap ? st[4*q+3] : e[4*q+3]);
    }
}

// ---------------------------------------------------------------------------
// Kernel 2: out[4096, 32000] = P @ W_out^T + b_out
// 2 vocab columns per thread (W regs: 32 instead of 64) -> ~80 regs total ->
// 3 CTAs/SM resident (occ ~37%) so the FFMA2 pipe stays fed across per-warp
// stall bubbles. Accumulators paired over K:
//   acc_c = { sum_even p*w , sum_odd p*w }  -> one horizontal add per col.
// P rows arrive as natural {p_2k,p_2k+1} pairs via 4x broadcast LDS.128,
// double-buffered across rows. Output stores use evict-streaming (.cs).
// ---------------------------------------------------------------------------
#define MTILE 64

__global__ __launch_bounds__(256, 3)
void out_gemm_kernel(const float* __restrict__ Wout,
                     const float* __restrict__ bout,
                     float* __restrict__ out, int V) {
    __shared__ __align__(16) ull sP[MTILE * 8];   // 4 KB natural-pair tile

    int row0 = blockIdx.y * MTILE;
    // cooperative tile load: MTILE*16 floats = 256 float4 -> 1 per thread
    ((float4*)sP)[threadIdx.x] =
        ((const float4*)(g_P + (size_t)row0 * 16))[threadIdx.x];
    __syncthreads();

    int v0 = blockIdx.x * 512 + threadIdx.x * 2;
    if (v0 >= V) return;

    // W pairs are natural-adjacent: wc[k] = {W[col][2k], W[col][2k+1]}
    ull w0[8], w1[8];
    {
        const float4* wa = (const float4*)(Wout + (size_t)v0 * 16);
        const float4* wb = (const float4*)(Wout + (size_t)(v0 + 1) * 16);
#pragma unroll
        for (int q = 0; q < 4; q++) {
            float4 t = wa[q];
            w0[2*q+0] = pack2(t.x, t.y);
            w0[2*q+1] = pack2(t.z, t.w);
        }
#pragma unroll
        for (int q = 0; q < 4; q++) {
            float4 t = wb[q];
            w1[2*q+0] = pack2(t.x, t.y);
            w1[2*q+1] = pack2(t.z, t.w);
        }
    }
    // bias folded into acc init: hadd({b,0} + sums) = sum + b
    ull bi0 = pack2(bout[v0], 0.f);
    ull bi1 = pack2(bout[v0 + 1], 0.f);

    float* outp = out + (size_t)row0 * V + v0;

    ull pA[8], pB[8];
    // preload row 0 into A (4x broadcast LDS.128)
    {
        const ulonglong2* r = (const ulonglong2*)(sP);
#pragma unroll
        for (int q = 0; q < 4; q++) { ulonglong2 t = r[q]; pA[2*q] = t.x; pA[2*q+1] = t.y; }
    }

#pragma unroll 1
    for (int m = 0; m < MTILE; m += 2) {
        // prefetch row m+1 into B
        {
            const ulonglong2* r = (const ulonglong2*)(sP + (m + 1) * 8);
#pragma unroll
            for (int q = 0; q < 4; q++) { ulonglong2 t = r[q]; pB[2*q] = t.x; pB[2*q+1] = t.y; }
        }
        // compute row m from A
        {
            ull a0 = bi0, a1 = bi1;
#pragma unroll
            for (int k = 0; k < 8; k++) {
                ull p = pA[k];
                a0 = fma2(p, w0[k], a0);
                a1 = fma2(p, w1[k], a1);
            }
            float2 r = make_float2(hadd2(a0), hadd2(a1));
            __stcs((float2*)outp, r);
            outp += V;
        }
        // prefetch row m+2 into A
        if (m + 2 < MTILE) {
            const ulonglong2* r = (const ulonglong2*)(sP + (m + 2) * 8);
#pragma unroll
            for (int q = 0; q < 4; q++) { ulonglong2 t = r[q]; pA[2*q] = t.x; pA[2*q+1] = t.y; }
        }
        // compute row m+1 from B
        {
            ull a0 = bi0, a1 = bi1;
#pragma unroll
            for (int k = 0; k < 8; k++) {
                ull p = pB[k];
                a0 = fma2(p, w0[k], a0);
                a1 = fma2(p, w1[k], a1);
            }
            float2 r = make_float2(hadd2(a0), hadd2(a1));
            __stcs((float2*)outp, r);
            outp += V;
        }
    }
}

// ---------------------------------------------------------------------------
// Launch
// ---------------------------------------------------------------------------
extern "C" void kernel_launch(void* const* d_in, const int* in_sizes, int n_in,
                              void* d_out, int out_size) {
    const int*   ids   = (const int*)d_in[0];
    const int*   mask  = (const int*)d_in[1];
    const float* We    = (const float*)d_in[2];
    const float* gates = (const float*)d_in[3];
    const float* Wout  = (const float*)d_in[4];
    const float* bout  = (const float*)d_in[5];
    float* out = (float*)d_out;

    int BS    = in_sizes[0];          // B*S = 4096
    int V     = in_sizes[5];          // 32000
    int depth = in_sizes[3] / 256;    // 2
    int S     = 2048;                 // problem shape (fixed)
    int B     = BS / S;               // 2

    prep_kernel<<<(BS + 127) / 128, 128>>>(ids, mask, We, gates, BS, depth, S, B);

    dim3 grid((V + 511) / 512, BS / MTILE);
    out_gemm_kernel<<<grid, 256>>>(Wout, bout, out, V);
}